// round 2
// baseline (speedup 1.0000x reference)
#include <cuda_runtime.h>

#define BB   8192
#define DD   128
#define NN   16384
#define INV_T 5.0f
#define KT   32

// ---------------- device scratch (no allocations allowed) ----------------
__device__ float    g_out[(size_t)NN * DD];   // normalized, concatenated rows
__device__ unsigned g_rm[NN];                 // cluster-membership bitmask per row
__device__ int      g_hq[NN];                 // hard cluster id per row
__device__ double   g_denom;
__device__ double   g_pos;                    // sum_i dot(out1_i, out2_i)
__device__ int      g_is64;

// packed f32x2 helpers (sm_103a: fma.rn.f32x2 doubles fp32 FMA throughput)
__device__ __forceinline__ unsigned long long pack2(float lo, float hi) {
    unsigned long long r;
    asm("mov.b64 %0, {%1, %2};" : "=l"(r) : "f"(lo), "f"(hi));
    return r;
}
__device__ __forceinline__ void unpack2(unsigned long long v, float& lo, float& hi) {
    asm("mov.b64 {%0, %1}, %2;" : "=f"(lo), "=f"(hi) : "l"(v));
}
__device__ __forceinline__ void ffma2(unsigned long long& d,
                                      unsigned long long a, unsigned long long b) {
    asm("fma.rn.f32x2 %0, %1, %2, %0;" : "+l"(d) : "l"(a), "l"(b));
}

// ---------------- init: zero accumulators + detect int32 vs int64 --------
__global__ void k_init(const int* __restrict__ nq32) {
    // If the integer inputs are int64, every odd 32-bit word is 0 (values < 10).
    // If int32, odd words are uniform in [0,10) -> essentially never all zero.
    int found = 0;
    for (int w = 2 * threadIdx.x + 1; w < 4096; w += 512)
        found |= (nq32[w] != 0);
    int any = __syncthreads_or(found);
    if (threadIdx.x == 0) {
        g_is64  = !any;
        g_denom = 0.0;
        g_pos   = 0.0;
    }
}

// ---------------- row normalize + positive-pair dot -----------------------
__global__ void k_norm(const float* __restrict__ x, const float* __restrict__ xa) {
    int r = blockIdx.x;           // 0..B-1
    int t = threadIdx.x;          // 0..127
    float xv = x[(size_t)r * DD + t];
    float av = xa[(size_t)r * DD + t];
    float sx = xv * xv, sa = av * av, sd = xv * av;
    #pragma unroll
    for (int o = 16; o; o >>= 1) {
        sx += __shfl_xor_sync(0xFFFFFFFFu, sx, o);
        sa += __shfl_xor_sync(0xFFFFFFFFu, sa, o);
        sd += __shfl_xor_sync(0xFFFFFFFFu, sd, o);
    }
    __shared__ float wsx[4], wsa[4], wsd[4];
    int w = t >> 5, l = t & 31;
    if (l == 0) { wsx[w] = sx; wsa[w] = sa; wsd[w] = sd; }
    __syncthreads();
    sx = wsx[0] + wsx[1] + wsx[2] + wsx[3];
    sa = wsa[0] + wsa[1] + wsa[2] + wsa[3];
    sd = wsd[0] + wsd[1] + wsd[2] + wsd[3];
    float inx = rsqrtf(sx), ina = rsqrtf(sa);
    g_out[(size_t)r * DD + t]        = xv * inx;
    g_out[(size_t)(BB + r) * DD + t] = av * ina;
    if (t == 0) atomicAdd(&g_pos, (double)(sd * inx * ina));
}

// ---------------- cluster masks -------------------------------------------
__global__ void k_mask(const void* __restrict__ hq, const void* __restrict__ nq, int K) {
    int n = blockIdx.x * blockDim.x + threadIdx.x;
    if (n >= NN) return;
    int is64 = g_is64;
    int hv = is64 ? (int)((const long long*)hq)[n] : ((const int*)hq)[n];
    unsigned m = 0;
    for (int k = 0; k < K; k++) {
        int v = is64 ? (int)((const long long*)nq)[(size_t)n * K + k]
                     : ((const int*)nq)[(size_t)n * K + k];
        m |= (1u << (v & 31));
    }
    g_hq[n] = hv & 31;
    g_rm[n] = m;
}

// ---------------- fused GEMM + exp + masked sum (upper triangle only) -----
// 128x128 tile, 256 threads, 8x8 micro-tile, packed f32x2 accumulators.
// Thread (tx,ty) owns rows ty*8..ty*8+7, col pairs (tx+32*q2, tx+32*q2+16).
__global__ void __launch_bounds__(256) k_main() {
    int bi = blockIdx.y, bj = blockIdx.x;
    if (bj < bi) return;                       // symmetric: only bj >= bi

    __shared__ float    As[128][KT + 1];       // stride 33 -> conflict-free
    __shared__ float    Bs[128][KT + 1];
    __shared__ unsigned rmI[128], rmJ[128];
    __shared__ int      hqI[128], hqJ[128];
    __shared__ float    red[8];

    int tx = threadIdx.x, ty = threadIdx.y;    // 16 x 16
    int tid = ty * 16 + tx;

    if (tid < 128) {
        rmI[tid] = g_rm[bi * 128 + tid];
        hqI[tid] = g_hq[bi * 128 + tid];
    } else {
        int t = tid - 128;
        rmJ[t] = g_rm[bj * 128 + t];
        hqJ[t] = g_hq[bj * 128 + t];
    }

    unsigned long long c2[8][4];               // [row r][col pair q2]
    #pragma unroll
    for (int r = 0; r < 8; r++)
        #pragma unroll
        for (int q = 0; q < 4; q++) c2[r][q] = 0ull;

    const float* Ag = g_out + (size_t)bi * 128 * DD;
    const float* Bg = g_out + (size_t)bj * 128 * DD;

    for (int k0 = 0; k0 < DD; k0 += KT) {
        // load chunk: 128 rows x 32 floats per tile, float4 coalesced global reads
        #pragma unroll
        for (int it = 0; it < 4; it++) {
            int idx = tid + it * 256;
            int i  = idx >> 3;
            int kk = (idx & 7) * 4;
            float4 va = *(const float4*)(Ag + (size_t)i * DD + k0 + kk);
            As[i][kk] = va.x; As[i][kk + 1] = va.y; As[i][kk + 2] = va.z; As[i][kk + 3] = va.w;
            float4 vb = *(const float4*)(Bg + (size_t)i * DD + k0 + kk);
            Bs[i][kk] = vb.x; Bs[i][kk + 1] = vb.y; Bs[i][kk + 2] = vb.z; Bs[i][kk + 3] = vb.w;
        }
        __syncthreads();

        #pragma unroll
        for (int k = 0; k < KT; k++) {
            unsigned long long a2[8], b2[4];
            #pragma unroll
            for (int r = 0; r < 8; r++) {
                float av = As[ty * 8 + r][k];
                a2[r] = pack2(av, av);
            }
            #pragma unroll
            for (int q = 0; q < 4; q++)
                b2[q] = pack2(Bs[tx + 32 * q][k], Bs[tx + 32 * q + 16][k]);
            #pragma unroll
            for (int r = 0; r < 8; r++)
                #pragma unroll
                for (int q = 0; q < 4; q++)
                    ffma2(c2[r][q], a2[r], b2[q]);
        }
        __syncthreads();
    }

    // epilogue: weight = m_ij + m_ji (counts both orders); diagonal tile only il<jl
    bool diag = (bi == bj);
    float tsum = 0.f;
    #pragma unroll
    for (int r = 0; r < 8; r++) {
        int il = ty * 8 + r;
        unsigned rmi = rmI[il];
        int      hqi = hqI[il];
        #pragma unroll
        for (int q = 0; q < 4; q++) {
            float s0, s1;
            unpack2(c2[r][q], s0, s1);
            int jl0 = tx + 32 * q;
            int jl1 = jl0 + 16;
            float w0 = (float)(((rmi >> hqJ[jl0]) & 1u) + ((rmJ[jl0] >> hqi) & 1u));
            float w1 = (float)(((rmi >> hqJ[jl1]) & 1u) + ((rmJ[jl1] >> hqi) & 1u));
            if (diag && il >= jl0) w0 = 0.f;
            if (diag && il >= jl1) w1 = 0.f;
            tsum += w0 * __expf(s0 * INV_T);
            tsum += w1 * __expf(s1 * INV_T);
        }
    }

    #pragma unroll
    for (int o = 16; o; o >>= 1) tsum += __shfl_xor_sync(0xFFFFFFFFu, tsum, o);
    if ((tid & 31) == 0) red[tid >> 5] = tsum;
    __syncthreads();
    if (tid == 0) {
        float s = 0.f;
        #pragma unroll
        for (int w = 0; w < 8; w++) s += red[w];
        atomicAdd(&g_denom, (double)s);
    }
}

// ---------------- finalize -------------------------------------------------
__global__ void k_fin(float* out) {
    if (threadIdx.x == 0)
        out[0] = (float)(log(g_denom) - g_pos / ((double)BB * 0.2));
}

// ---------------- launch ---------------------------------------------------
extern "C" void kernel_launch(void* const* d_in, const int* in_sizes, int n_in,
                              void* d_out, int out_size) {
    const float* x  = (const float*)d_in[0];
    const float* xa = (const float*)d_in[1];
    const void*  hq = d_in[2];
    const void*  nq = d_in[3];
    int K = in_sizes[3] / NN;                 // 10

    k_init<<<1, 256>>>((const int*)nq);
    k_norm<<<BB, 128>>>(x, xa);
    k_mask<<<(NN + 255) / 256, 256>>>(hq, nq, K);
    k_main<<<dim3(128, 128), dim3(16, 16)>>>();
    k_fin<<<1, 32>>>((float*)d_out);
}

// round 8
// speedup vs baseline: 2.9958x; 2.9958x over previous
#include <cuda_runtime.h>
#include <cuda_bf16.h>
#include <cstdint>

#define BB   8192
#define DD   128
#define NN   16384
#define INV_T 5.0f
#define SROW 72     // padded smem row (shorts): 64 data + 8 pad -> conflict-free

// ---------------- device scratch ----------------
__device__ __align__(16) __nv_bfloat16 g_hi[(size_t)NN * DD];
__device__ __align__(16) __nv_bfloat16 g_lo[(size_t)NN * DD];
__device__ unsigned g_rm[NN];
__device__ int      g_hq[NN];
__device__ double   g_denom;
__device__ double   g_pos;
__device__ int      g_is64;

// bf16 tensor-core mma (sm_80+ baseline PTX -> HMMA.16816 on sm_103)
__device__ __forceinline__ void mma16816(float* c, const uint32_t* a, const uint32_t* b) {
    asm volatile(
        "mma.sync.aligned.m16n8k16.row.col.f32.bf16.bf16.f32 "
        "{%0,%1,%2,%3}, {%4,%5,%6,%7}, {%8,%9}, {%0,%1,%2,%3};"
        : "+f"(c[0]), "+f"(c[1]), "+f"(c[2]), "+f"(c[3])
        : "r"(a[0]), "r"(a[1]), "r"(a[2]), "r"(a[3]), "r"(b[0]), "r"(b[1]));
}

// ---------------- init: zero accumulators + detect int32 vs int64 --------
__global__ void k_init(const int* __restrict__ nq32) {
    int found = 0;
    for (int w = 2 * threadIdx.x + 1; w < 4096; w += 512)
        found |= (nq32[w] != 0);
    int any = __syncthreads_or(found);
    if (threadIdx.x == 0) {
        g_is64  = !any;
        g_denom = 0.0;
        g_pos   = 0.0;
    }
}

// ---------------- normalize + hi/lo bf16 split + positive-pair dot --------
__global__ void k_norm(const float* __restrict__ x, const float* __restrict__ xa) {
    int r = blockIdx.x;
    int t = threadIdx.x;                         // 0..127
    float xv = x[(size_t)r * DD + t];
    float av = xa[(size_t)r * DD + t];
    float sx = xv * xv, sa = av * av, sd = xv * av;
    #pragma unroll
    for (int o = 16; o; o >>= 1) {
        sx += __shfl_xor_sync(0xFFFFFFFFu, sx, o);
        sa += __shfl_xor_sync(0xFFFFFFFFu, sa, o);
        sd += __shfl_xor_sync(0xFFFFFFFFu, sd, o);
    }
    __shared__ float wsx[4], wsa[4], wsd[4];
    int w = t >> 5, l = t & 31;
    if (l == 0) { wsx[w] = sx; wsa[w] = sa; wsd[w] = sd; }
    __syncthreads();
    sx = wsx[0] + wsx[1] + wsx[2] + wsx[3];
    sa = wsa[0] + wsa[1] + wsa[2] + wsa[3];
    sd = wsd[0] + wsd[1] + wsd[2] + wsd[3];
    float inx = rsqrtf(sx), ina = rsqrtf(sa);

    float v1 = xv * inx;
    float v2 = av * ina;
    __nv_bfloat16 h1 = __float2bfloat16(v1);
    __nv_bfloat16 h2 = __float2bfloat16(v2);
    g_hi[(size_t)r * DD + t]        = h1;
    g_lo[(size_t)r * DD + t]        = __float2bfloat16(v1 - __bfloat162float(h1));
    g_hi[(size_t)(BB + r) * DD + t] = h2;
    g_lo[(size_t)(BB + r) * DD + t] = __float2bfloat16(v2 - __bfloat162float(h2));
    if (t == 0) atomicAdd(&g_pos, (double)(sd * inx * ina));
}

// ---------------- cluster masks -------------------------------------------
__global__ void k_mask(const void* __restrict__ hq, const void* __restrict__ nq, int K) {
    int n = blockIdx.x * blockDim.x + threadIdx.x;
    if (n >= NN) return;
    int is64 = g_is64;
    int hv = is64 ? (int)((const long long*)hq)[n] : ((const int*)hq)[n];
    unsigned m = 0;
    for (int k = 0; k < K; k++) {
        int v = is64 ? (int)((const long long*)nq)[(size_t)n * K + k]
                     : ((const int*)nq)[(size_t)n * K + k];
        m |= (1u << (v & 31));
    }
    g_hq[n] = hv & 31;
    g_rm[n] = m;
}

// load 128x64 bf16 chunk (col offset c4 in uint4 units) into padded smem tile
#define LOAD_TILE(S, Gl, c4)                                              \
    do {                                                                  \
        _Pragma("unroll")                                                 \
        for (int it = 0; it < 4; it++) {                                  \
            int idx = tid + it * 256;                                     \
            int rr = idx >> 3, qq = idx & 7;                              \
            uint4 v = (Gl)[rr * 16 + (c4) + qq];                          \
            *(uint4*)&(S)[rr][qq * 8] = v;                                \
        }                                                                 \
    } while (0)

// ---------------- fused GEMM(HMMA) + exp + masked sum (upper triangle) ----
// 128x128 tile, 256 thr = 8 warps (2 m x 4 n), warp tile 64x32 (4x4 frags).
// S = (Ahi + Alo) . Bhi^T, fp32 accum. K as 4 chunks of 64 (2 pass x 2 half).
__global__ void __launch_bounds__(256, 2) k_main() {
    int bi = blockIdx.y, bj = blockIdx.x;
    if (bj < bi) return;                       // symmetric: only bj >= bi

    __shared__ unsigned short As[128][SROW];
    __shared__ unsigned short Bs[128][SROW];
    __shared__ unsigned rmI[128], rmJ[128];
    __shared__ int      hqI[128], hqJ[128];
    __shared__ float    red[8];

    int tid  = threadIdx.x;
    int wid  = tid >> 5, lane = tid & 31;
    int wm   = wid & 1,  wn   = wid >> 1;      // 2 x 4 warps
    int g    = lane >> 2, t4  = lane & 3;

    if (tid < 128) {
        rmI[tid] = g_rm[bi * 128 + tid];
        hqI[tid] = g_hq[bi * 128 + tid];
    } else {
        int t = tid - 128;
        rmJ[t] = g_rm[bj * 128 + t];
        hqJ[t] = g_hq[bj * 128 + t];
    }

    float acc[4][4][4];                        // [mb][nb][reg]
    #pragma unroll
    for (int mb = 0; mb < 4; mb++)
        #pragma unroll
        for (int nb = 0; nb < 4; nb++)
            #pragma unroll
            for (int r = 0; r < 4; r++) acc[mb][nb][r] = 0.f;

    const uint4* Ahi = (const uint4*)(g_hi + (size_t)bi * 128 * DD);
    const uint4* Alo = (const uint4*)(g_lo + (size_t)bi * 128 * DD);
    const uint4* Bgl = (const uint4*)(g_hi + (size_t)bj * 128 * DD);

    #pragma unroll
    for (int half = 0; half < 2; half++) {
        int c4 = half * 8;                     // 64 bf16 = 8 uint4
        #pragma unroll
        for (int pass = 0; pass < 2; pass++) {
            __syncthreads();                   // protect previous compute
            if (pass == 0) {
                LOAD_TILE(Bs, Bgl, c4);
                LOAD_TILE(As, Ahi, c4);
            } else {
                LOAD_TILE(As, Alo, c4);
            }
            __syncthreads();

            #pragma unroll
            for (int ks = 0; ks < 4; ks++) {
                int kc = ks * 16 + 2 * t4;     // this thread's base col (shorts)
                uint32_t a[4][4], b[4][2];
                #pragma unroll
                for (int mb = 0; mb < 4; mb++) {
                    int m = wm * 64 + mb * 16 + g;
                    a[mb][0] = *(const uint32_t*)&As[m][kc];
                    a[mb][1] = *(const uint32_t*)&As[m + 8][kc];
                    a[mb][2] = *(const uint32_t*)&As[m][kc + 8];
                    a[mb][3] = *(const uint32_t*)&As[m + 8][kc + 8];
                }
                #pragma unroll
                for (int nb = 0; nb < 4; nb++) {
                    int n = wn * 32 + nb * 8 + g;
                    b[nb][0] = *(const uint32_t*)&Bs[n][kc];
                    b[nb][1] = *(const uint32_t*)&Bs[n][kc + 8];
                }
                #pragma unroll
                for (int mb = 0; mb < 4; mb++)
                    #pragma unroll
                    for (int nb = 0; nb < 4; nb++)
                        mma16816(acc[mb][nb], a[mb], b[nb]);
            }
        }
    }

    // epilogue: weight = m_ij + m_ji; diagonal tile keeps only il<jl
    bool diag = (bi == bj);
    float tsum = 0.f;
    #pragma unroll
    for (int mb = 0; mb < 4; mb++) {
        #pragma unroll
        for (int r = 0; r < 4; r++) {
            int row = wm * 64 + mb * 16 + g + ((r & 2) ? 8 : 0);
            unsigned rmi = rmI[row];
            int      hqi = hqI[row];
            #pragma unroll
            for (int nb = 0; nb < 4; nb++) {
                int col = wn * 32 + nb * 8 + 2 * t4 + (r & 1);
                float s = acc[mb][nb][r];
                float w = (float)(((rmi >> hqJ[col]) & 1u) + ((rmJ[col] >> hqi) & 1u));
                if (diag && row >= col) w = 0.f;
                tsum += w * __expf(s * INV_T);
            }
        }
    }

    #pragma unroll
    for (int o = 16; o; o >>= 1) tsum += __shfl_xor_sync(0xFFFFFFFFu, tsum, o);
    if (lane == 0) red[wid] = tsum;
    __syncthreads();
    if (tid == 0) {
        float s = 0.f;
        #pragma unroll
        for (int w = 0; w < 8; w++) s += red[w];
        atomicAdd(&g_denom, (double)s);
    }
}

// ---------------- finalize -------------------------------------------------
__global__ void k_fin(float* out) {
    if (threadIdx.x == 0)
        out[0] = (float)(log(g_denom) - g_pos / ((double)BB * 0.2));
}

// ---------------- launch ---------------------------------------------------
extern "C" void kernel_launch(void* const* d_in, const int* in_sizes, int n_in,
                              void* d_out, int out_size) {
    const float* x  = (const float*)d_in[0];
    const float* xa = (const float*)d_in[1];
    const void*  hq = d_in[2];
    const void*  nq = d_in[3];
    int K = in_sizes[3] / NN;                 // 10

    k_init<<<1, 256>>>((const int*)nq);
    k_norm<<<BB, 128>>>(x, xa);
    k_mask<<<(NN + 255) / 256, 256>>>(hq, nq, K);
    k_main<<<dim3(128, 128), 256>>>();
    k_fin<<<1, 32>>>((float*)d_out);
}

// round 12
// speedup vs baseline: 4.6790x; 1.5619x over previous
#include <cuda_runtime.h>
#include <cuda_bf16.h>
#include <cstdint>

#define BB   8192
#define DD   128
#define NN   16384
#define INV_T 5.0f
#define SROW 72     // padded smem row (shorts): 64 data + 8 pad -> ldmatrix conflict-free

// ---------------- device scratch ----------------
__device__ __align__(16) __nv_bfloat16 g_hi[(size_t)NN * DD];
__device__ unsigned g_rm[NN];
__device__ int      g_hq[NN];
__device__ double   g_denom;
__device__ double   g_pos;
__device__ int      g_is64;

// bf16 tensor-core mma (sm_80+ baseline PTX)
__device__ __forceinline__ void mma16816(float* c, const uint32_t* a, const uint32_t* b) {
    asm volatile(
        "mma.sync.aligned.m16n8k16.row.col.f32.bf16.bf16.f32 "
        "{%0,%1,%2,%3}, {%4,%5,%6,%7}, {%8,%9}, {%0,%1,%2,%3};"
        : "+f"(c[0]), "+f"(c[1]), "+f"(c[2]), "+f"(c[3])
        : "r"(a[0]), "r"(a[1]), "r"(a[2]), "r"(a[3]), "r"(b[0]), "r"(b[1]));
}
__device__ __forceinline__ void ldsm4(uint32_t& r0, uint32_t& r1, uint32_t& r2, uint32_t& r3,
                                      uint32_t addr) {
    asm volatile("ldmatrix.sync.aligned.m8n8.x4.shared.b16 {%0,%1,%2,%3}, [%4];"
                 : "=r"(r0), "=r"(r1), "=r"(r2), "=r"(r3) : "r"(addr));
}
__device__ __forceinline__ uint32_t smem_u32(const void* p) {
    uint32_t a;
    asm("{ .reg .u64 t; cvta.to.shared.u64 t, %1; cvt.u32.u64 %0, t; }" : "=r"(a) : "l"(p));
    return a;
}

// ---------------- init: zero accumulators + detect int32 vs int64 --------
__global__ void k_init(const int* __restrict__ nq32) {
    int found = 0;
    for (int w = 2 * threadIdx.x + 1; w < 4096; w += 512)
        found |= (nq32[w] != 0);
    int any = __syncthreads_or(found);
    if (threadIdx.x == 0) {
        g_is64  = !any;
        g_denom = 0.0;
        g_pos   = 0.0;
    }
}

// ---------------- normalize + bf16 round + positive-pair dot --------------
__global__ void k_norm(const float* __restrict__ x, const float* __restrict__ xa) {
    int r = blockIdx.x;
    int t = threadIdx.x;                         // 0..127
    float xv = x[(size_t)r * DD + t];
    float av = xa[(size_t)r * DD + t];
    float sx = xv * xv, sa = av * av, sd = xv * av;
    #pragma unroll
    for (int o = 16; o; o >>= 1) {
        sx += __shfl_xor_sync(0xFFFFFFFFu, sx, o);
        sa += __shfl_xor_sync(0xFFFFFFFFu, sa, o);
        sd += __shfl_xor_sync(0xFFFFFFFFu, sd, o);
    }
    __shared__ float wsx[4], wsa[4], wsd[4];
    int w = t >> 5, l = t & 31;
    if (l == 0) { wsx[w] = sx; wsa[w] = sa; wsd[w] = sd; }
    __syncthreads();
    sx = wsx[0] + wsx[1] + wsx[2] + wsx[3];
    sa = wsa[0] + wsa[1] + wsa[2] + wsa[3];
    sd = wsd[0] + wsd[1] + wsd[2] + wsd[3];
    float inx = rsqrtf(sx), ina = rsqrtf(sa);

    g_hi[(size_t)r * DD + t]        = __float2bfloat16(xv * inx);
    g_hi[(size_t)(BB + r) * DD + t] = __float2bfloat16(av * ina);
    if (t == 0) atomicAdd(&g_pos, (double)(sd * inx * ina));
}

// ---------------- cluster masks -------------------------------------------
__global__ void k_mask(const void* __restrict__ hq, const void* __restrict__ nq, int K) {
    int n = blockIdx.x * blockDim.x + threadIdx.x;
    if (n >= NN) return;
    int is64 = g_is64;
    int hv = is64 ? (int)((const long long*)hq)[n] : ((const int*)hq)[n];
    unsigned m = 0;
    for (int k = 0; k < K; k++) {
        int v = is64 ? (int)((const long long*)nq)[(size_t)n * K + k]
                     : ((const int*)nq)[(size_t)n * K + k];
        m |= (1u << (v & 31));
    }
    g_hq[n] = hv & 31;
    g_rm[n] = m;
}

// load 128x64 bf16 chunk (col offset c4 in uint4 units), 128 threads
#define LOAD_TILE(S, Gl, c4)                                              \
    do {                                                                  \
        _Pragma("unroll")                                                 \
        for (int it = 0; it < 8; it++) {                                  \
            int idx = tid + it * 128;                                     \
            int rr = idx >> 3, qq = idx & 7;                              \
            uint4 v = (Gl)[rr * 16 + (c4) + qq];                          \
            *(uint4*)&(S)[rr][qq * 8] = v;                                \
        }                                                                 \
    } while (0)

// ---------------- fused GEMM(HMMA) + exp + masked sum (upper triangle) ----
// Block 128x128, 128 thr = 4 warps (2m x 2n), warp tile 64x64 (4m x 8n frags).
// S = x_hi . y_hi^T (bf16, fp32 accum). K as 2 chunks of 64. ldmatrix.x4.
__global__ void __launch_bounds__(128) k_main() {
    int bi = blockIdx.y, bj = blockIdx.x;
    if (bj < bi) return;                       // symmetric: only bj >= bi

    __shared__ unsigned short As[128][SROW];
    __shared__ unsigned short Bs[128][SROW];
    __shared__ unsigned rmI[128], rmJ[128];
    __shared__ int      hqI[128], hqJ[128];
    __shared__ float    red[4];

    int tid  = threadIdx.x;
    int wid  = tid >> 5, lane = tid & 31;
    int wm   = wid & 1,  wn   = wid >> 1;      // 2 x 2 warps
    int g    = lane >> 2, t4  = lane & 3;

    rmI[tid] = g_rm[bi * 128 + tid];
    hqI[tid] = g_hq[bi * 128 + tid];
    rmJ[tid] = g_rm[bj * 128 + tid];
    hqJ[tid] = g_hq[bj * 128 + tid];

    float acc[4][8][4];                        // [mb][nb][reg]
    #pragma unroll
    for (int mb = 0; mb < 4; mb++)
        #pragma unroll
        for (int nb = 0; nb < 8; nb++)
            #pragma unroll
            for (int r = 0; r < 4; r++) acc[mb][nb][r] = 0.f;

    const uint4* Agl = (const uint4*)(g_hi + (size_t)bi * 128 * DD);
    const uint4* Bgl = (const uint4*)(g_hi + (size_t)bj * 128 * DD);

    // per-thread ldmatrix addresses (within 64-row warp slices)
    int m0 = wm * 64, n0 = wn * 64;
    uint32_t arow = smem_u32(&As[0][0])
                  + (uint32_t)((m0 + (lane & 15)) * (SROW * 2))
                  + (uint32_t)((lane >> 4) << 4);
    uint32_t brow = smem_u32(&Bs[0][0])
                  + (uint32_t)((n0 + ((lane >> 4) << 3) + (lane & 7)) * (SROW * 2))
                  + (uint32_t)(((lane >> 3) & 1) << 4);

    #pragma unroll
    for (int half = 0; half < 2; half++) {
        int c4 = half * 8;                     // 64 bf16 = 8 uint4
        __syncthreads();                       // protect previous chunk's smem
        LOAD_TILE(As, Agl, c4);
        LOAD_TILE(Bs, Bgl, c4);
        __syncthreads();

        #pragma unroll
        for (int ks = 0; ks < 4; ks++) {
            uint32_t koff = (uint32_t)(ks * 32);
            uint32_t b[8][2];
            #pragma unroll
            for (int nbp = 0; nbp < 4; nbp++)
                ldsm4(b[2 * nbp][0], b[2 * nbp][1], b[2 * nbp + 1][0], b[2 * nbp + 1][1],
                      brow + (uint32_t)(nbp * 16 * (SROW * 2)) + koff);
            uint32_t a[4][4];
            #pragma unroll
            for (int mb = 0; mb < 4; mb++)
                ldsm4(a[mb][0], a[mb][1], a[mb][2], a[mb][3],
                      arow + (uint32_t)(mb * 16 * (SROW * 2)) + koff);
            #pragma unroll
            for (int mb = 0; mb < 4; mb++)
                #pragma unroll
                for (int nb = 0; nb < 8; nb++)
                    mma16816(acc[mb][nb], a[mb], b[nb]);
        }
    }

    // epilogue: weight = m_ij + m_ji; diagonal tile keeps only row<col
    bool diag = (bi == bj);
    float tsum = 0.f;
    #pragma unroll
    for (int mb = 0; mb < 4; mb++) {
        #pragma unroll
        for (int rr = 0; rr < 2; rr++) {
            int row = m0 + mb * 16 + g + rr * 8;
            unsigned rmi = rmI[row];
            int      hqi = hqI[row];
            #pragma unroll
            for (int nb = 0; nb < 8; nb++) {
                #pragma unroll
                for (int rc = 0; rc < 2; rc++) {
                    int col = n0 + nb * 8 + 2 * t4 + rc;
                    float s = acc[mb][nb][rr * 2 + rc];
                    float w = (float)(((rmi >> hqJ[col]) & 1u) + ((rmJ[col] >> hqi) & 1u));
                    if (diag && row >= col) w = 0.f;
                    tsum += w * __expf(s * INV_T);
                }
            }
        }
    }

    #pragma unroll
    for (int o = 16; o; o >>= 1) tsum += __shfl_xor_sync(0xFFFFFFFFu, tsum, o);
    if (lane == 0) red[wid] = tsum;
    __syncthreads();
    if (tid == 0)
        atomicAdd(&g_denom, (double)(red[0] + red[1] + red[2] + red[3]));
}

// ---------------- finalize -------------------------------------------------
__global__ void k_fin(float* out) {
    if (threadIdx.x == 0)
        out[0] = (float)(log(g_denom) - g_pos / ((double)BB * 0.2));
}

// ---------------- launch ---------------------------------------------------
extern "C" void kernel_launch(void* const* d_in, const int* in_sizes, int n_in,
                              void* d_out, int out_size) {
    const float* x  = (const float*)d_in[0];
    const float* xa = (const float*)d_in[1];
    const void*  hq = d_in[2];
    const void*  nq = d_in[3];
    int K = in_sizes[3] / NN;                 // 10

    k_init<<<1, 256>>>((const int*)nq);
    k_norm<<<BB, 128>>>(x, xa);
    k_mask<<<(NN + 255) / 256, 256>>>(hq, nq, K);
    k_main<<<dim3(128, 128), 128>>>();
    k_fin<<<1, 32>>>((float*)d_out);
}

// round 14
// speedup vs baseline: 4.9597x; 1.0600x over previous
#include <cuda_runtime.h>
#include <cuda_bf16.h>
#include <cstdint>

#define BB   8192
#define DD   128
#define NN   16384
#define L2E5 7.21347520444482f   // 5 * log2(e)
#define SROW2 40                 // chunk row: 32 data + 8 pad shorts (80B, 16B-mult, ldsm conflict-free)
#define BUFB  10240              // one chunk buffer: 128*40*2 bytes

// ---------------- device scratch ----------------
__device__ __align__(16) __nv_bfloat16 g_hi[(size_t)NN * DD];
__device__ unsigned g_rm[NN];
__device__ int      g_hq[NN];
__device__ double   g_denom;
__device__ double   g_pos;
__device__ int      g_is64;

// bf16 tensor-core mma (sm_80+ baseline PTX)
__device__ __forceinline__ void mma16816(float* c, const uint32_t* a, const uint32_t* b) {
    asm volatile(
        "mma.sync.aligned.m16n8k16.row.col.f32.bf16.bf16.f32 "
        "{%0,%1,%2,%3}, {%4,%5,%6,%7}, {%8,%9}, {%0,%1,%2,%3};"
        : "+f"(c[0]), "+f"(c[1]), "+f"(c[2]), "+f"(c[3])
        : "r"(a[0]), "r"(a[1]), "r"(a[2]), "r"(a[3]), "r"(b[0]), "r"(b[1]));
}
__device__ __forceinline__ void ldsm4(uint32_t& r0, uint32_t& r1, uint32_t& r2, uint32_t& r3,
                                      uint32_t addr) {
    asm volatile("ldmatrix.sync.aligned.m8n8.x4.shared.b16 {%0,%1,%2,%3}, [%4];"
                 : "=r"(r0), "=r"(r1), "=r"(r2), "=r"(r3) : "r"(addr));
}
__device__ __forceinline__ uint32_t smem_u32(const void* p) {
    uint32_t a;
    asm("{ .reg .u64 t; cvta.to.shared.u64 t, %1; cvt.u32.u64 %0, t; }" : "=r"(a) : "l"(p));
    return a;
}
__device__ __forceinline__ void cpa16(uint32_t d, const void* s) {
    asm volatile("cp.async.cg.shared.global [%0], [%1], 16;" :: "r"(d), "l"(s) : "memory");
}
#define CPA_COMMIT() asm volatile("cp.async.commit_group;" ::: "memory")
#define CPA_WAIT(n)  asm volatile("cp.async.wait_group %0;" :: "n"(n) : "memory")
__device__ __forceinline__ float ex2f(float x) {
    float r;
    asm("ex2.approx.f32 %0, %1;" : "=f"(r) : "f"(x));
    return r;
}

// ---------------- init: zero accumulators + detect int32 vs int64 --------
__global__ void k_init(const int* __restrict__ nq32) {
    int found = 0;
    for (int w = 2 * threadIdx.x + 1; w < 4096; w += 512)
        found |= (nq32[w] != 0);
    int any = __syncthreads_or(found);
    if (threadIdx.x == 0) {
        g_is64  = !any;
        g_denom = 0.0;
        g_pos   = 0.0;
    }
}

// ---------------- normalize + bf16 round + positive-pair dot --------------
__global__ void k_norm(const float* __restrict__ x, const float* __restrict__ xa) {
    int r = blockIdx.x;
    int t = threadIdx.x;                         // 0..127
    float xv = x[(size_t)r * DD + t];
    float av = xa[(size_t)r * DD + t];
    float sx = xv * xv, sa = av * av, sd = xv * av;
    #pragma unroll
    for (int o = 16; o; o >>= 1) {
        sx += __shfl_xor_sync(0xFFFFFFFFu, sx, o);
        sa += __shfl_xor_sync(0xFFFFFFFFu, sa, o);
        sd += __shfl_xor_sync(0xFFFFFFFFu, sd, o);
    }
    __shared__ float wsx[4], wsa[4], wsd[4];
    int w = t >> 5, l = t & 31;
    if (l == 0) { wsx[w] = sx; wsa[w] = sa; wsd[w] = sd; }
    __syncthreads();
    sx = wsx[0] + wsx[1] + wsx[2] + wsx[3];
    sa = wsa[0] + wsa[1] + wsa[2] + wsa[3];
    sd = wsd[0] + wsd[1] + wsd[2] + wsd[3];
    float inx = rsqrtf(sx), ina = rsqrtf(sa);

    g_hi[(size_t)r * DD + t]        = __float2bfloat16(xv * inx);
    g_hi[(size_t)(BB + r) * DD + t] = __float2bfloat16(av * ina);
    if (t == 0) atomicAdd(&g_pos, (double)(sd * inx * ina));
}

// ---------------- cluster masks -------------------------------------------
__global__ void k_mask(const void* __restrict__ hq, const void* __restrict__ nq, int K) {
    int n = blockIdx.x * blockDim.x + threadIdx.x;
    if (n >= NN) return;
    int is64 = g_is64;
    int hv = is64 ? (int)((const long long*)hq)[n] : ((const int*)hq)[n];
    unsigned m = 0;
    for (int k = 0; k < K; k++) {
        int v = is64 ? (int)((const long long*)nq)[(size_t)n * K + k]
                     : ((const int*)nq)[(size_t)n * K + k];
        m |= (1u << (v & 31));
    }
    g_hq[n] = hv & 31;
    g_rm[n] = m;
}

// ---------------- fused GEMM(HMMA) + exp + masked sum (upper triangle) ----
// Block 128x128, 128 thr = 4 warps (2m x 2n), warp tile 64x64.
// K as 4 chunks of 32, cp.async double-buffered. Packed-mask epilogue.
__global__ void __launch_bounds__(128) k_main() {
    int bi = blockIdx.y, bj = blockIdx.x;
    if (bj < bi) return;                       // symmetric: only bj >= bi

    __shared__ __align__(16) unsigned short As2[2][128][SROW2];
    __shared__ __align__(16) unsigned short Bs2[2][128][SROW2];
    __shared__ unsigned pkI[128], pkJ[128];    // rm | (hq<<12)
    __shared__ float    red[4];

    int tid  = threadIdx.x;
    int wid  = tid >> 5, lane = tid & 31;
    int wm   = wid & 1,  wn   = wid >> 1;      // 2 x 2 warps
    int g    = lane >> 2, t4  = lane & 3;

    pkI[tid] = g_rm[bi * 128 + tid] | ((unsigned)g_hq[bi * 128 + tid] << 12);
    pkJ[tid] = g_rm[bj * 128 + tid] | ((unsigned)g_hq[bj * 128 + tid] << 12);

    float acc[4][8][4];                        // [mb][nb][reg]
    #pragma unroll
    for (int mb = 0; mb < 4; mb++)
        #pragma unroll
        for (int nb = 0; nb < 8; nb++)
            #pragma unroll
            for (int r = 0; r < 4; r++) acc[mb][nb][r] = 0.f;

    const uint4* Agl = (const uint4*)(g_hi + (size_t)bi * 128 * DD);
    const uint4* Bgl = (const uint4*)(g_hi + (size_t)bj * 128 * DD);
    uint32_t smA = smem_u32(&As2[0][0][0]);
    uint32_t smB = smem_u32(&Bs2[0][0][0]);

    // per-thread ldmatrix base addresses (within 64-row warp slices)
    int m0 = wm * 64, n0 = wn * 64;
    uint32_t arow = smA + (uint32_t)((m0 + (lane & 15)) * (SROW2 * 2))
                  + (uint32_t)((lane >> 4) << 4);
    uint32_t brow = smB + (uint32_t)((n0 + ((lane >> 4) << 3) + (lane & 7)) * (SROW2 * 2))
                  + (uint32_t)(((lane >> 3) & 1) << 4);

    // async-load one 32-col chunk (c) into buffer (f)
    #define LOAD_CHUNK(c, f)                                              \
        do {                                                              \
            _Pragma("unroll")                                             \
            for (int it = 0; it < 4; it++) {                              \
                int idx = tid + it * 128;                                 \
                int rr2 = idx >> 2, qq = idx & 3;                         \
                uint32_t off = (uint32_t)(f) * BUFB                       \
                             + (uint32_t)(rr2 * (SROW2 * 2) + qq * 16);   \
                cpa16(smA + off, Agl + rr2 * 16 + (c) * 4 + qq);          \
                cpa16(smB + off, Bgl + rr2 * 16 + (c) * 4 + qq);          \
            }                                                             \
            CPA_COMMIT();                                                 \
        } while (0)

    LOAD_CHUNK(0, 0);

    #pragma unroll
    for (int c = 0; c < 4; c++) {
        if (c < 3) {
            LOAD_CHUNK(c + 1, (c + 1) & 1);
            CPA_WAIT(1);
        } else {
            CPA_WAIT(0);
        }
        __syncthreads();
        uint32_t boff = (uint32_t)(c & 1) * BUFB;
        #pragma unroll
        for (int ks = 0; ks < 2; ks++) {
            uint32_t koff = boff + (uint32_t)(ks * 32);
            uint32_t b[8][2];
            #pragma unroll
            for (int nbp = 0; nbp < 4; nbp++)
                ldsm4(b[2 * nbp][0], b[2 * nbp][1], b[2 * nbp + 1][0], b[2 * nbp + 1][1],
                      brow + (uint32_t)(nbp * 16 * (SROW2 * 2)) + koff);
            uint32_t a[4][4];
            #pragma unroll
            for (int mb = 0; mb < 4; mb++)
                ldsm4(a[mb][0], a[mb][1], a[mb][2], a[mb][3],
                      arow + (uint32_t)(mb * 16 * (SROW2 * 2)) + koff);
            #pragma unroll
            for (int mb = 0; mb < 4; mb++)
                #pragma unroll
                for (int nb = 0; nb < 8; nb++)
                    mma16816(acc[mb][nb], a[mb], b[nb]);
        }
        __syncthreads();                       // all reads of this buffer done
    }
    #undef LOAD_CHUNK

    // ---- epilogue: packed masks, cols outer / rows inner (row masks in regs) ----
    unsigned rmi8[8];
    int      hqi8[8], row8[8];
    #pragma unroll
    for (int mb = 0; mb < 4; mb++)
        #pragma unroll
        for (int rr = 0; rr < 2; rr++) {
            int k = mb * 2 + rr;
            row8[k] = m0 + mb * 16 + g + rr * 8;
            unsigned p = pkI[row8[k]];
            rmi8[k] = p & 0xFFFu;
            hqi8[k] = (int)(p >> 12);
        }

    float t0 = 0.f, t1 = 0.f;
    if (bi != bj) {
        #pragma unroll
        for (int nb = 0; nb < 8; nb++)
            #pragma unroll
            for (int rc = 0; rc < 2; rc++) {
                int col = n0 + nb * 8 + 2 * t4 + rc;
                unsigned pj = pkJ[col];
                unsigned rmj = pj & 0xFFFu;
                int      hqj = (int)(pj >> 12);
                #pragma unroll
                for (int k = 0; k < 8; k++) {
                    float s = acc[k >> 1][nb][(k & 1) * 2 + rc];
                    float e = ex2f(s * L2E5);
                    unsigned w = ((rmi8[k] >> hqj) & 1u) + ((rmj >> hqi8[k]) & 1u);
                    if (rc) t1 = fmaf((float)w, e, t1);
                    else    t0 = fmaf((float)w, e, t0);
                }
            }
    } else {
        #pragma unroll
        for (int nb = 0; nb < 8; nb++)
            #pragma unroll
            for (int rc = 0; rc < 2; rc++) {
                int col = n0 + nb * 8 + 2 * t4 + rc;
                unsigned pj = pkJ[col];
                unsigned rmj = pj & 0xFFFu;
                int      hqj = (int)(pj >> 12);
                #pragma unroll
                for (int k = 0; k < 8; k++) {
                    float s = acc[k >> 1][nb][(k & 1) * 2 + rc];
                    float e = ex2f(s * L2E5);
                    unsigned w = ((rmi8[k] >> hqj) & 1u) + ((rmj >> hqi8[k]) & 1u);
                    if (row8[k] >= col) w = 0u;
                    if (rc) t1 = fmaf((float)w, e, t1);
                    else    t0 = fmaf((float)w, e, t0);
                }
            }
    }

    float tsum = t0 + t1;
    #pragma unroll
    for (int o = 16; o; o >>= 1) tsum += __shfl_xor_sync(0xFFFFFFFFu, tsum, o);
    if (lane == 0) red[wid] = tsum;
    __syncthreads();
    if (tid == 0)
        atomicAdd(&g_denom, (double)(red[0] + red[1] + red[2] + red[3]));
}

// ---------------- finalize -------------------------------------------------
__global__ void k_fin(float* out) {
    if (threadIdx.x == 0)
        out[0] = (float)(log(g_denom) - g_pos / ((double)BB * 0.2));
}

// ---------------- launch ---------------------------------------------------
extern "C" void kernel_launch(void* const* d_in, const int* in_sizes, int n_in,
                              void* d_out, int out_size) {
    const float* x  = (const float*)d_in[0];
    const float* xa = (const float*)d_in[1];
    const void*  hq = d_in[2];
    const void*  nq = d_in[3];
    int K = in_sizes[3] / NN;                 // 10

    k_init<<<1, 256>>>((const int*)nq);
    k_norm<<<BB, 128>>>(x, xa);
    k_mask<<<(NN + 255) / 256, 256>>>(hq, nq, K);
    k_main<<<dim3(128, 128), 128>>>();
    k_fin<<<1, 32>>>((float*)d_out);
}

// round 15
// speedup vs baseline: 5.0992x; 1.0281x over previous
#include <cuda_runtime.h>
#include <cuda_bf16.h>
#include <cstdint>

#define BB   8192
#define DD   128
#define NN   16384
#define L2E5 7.21347520444482f   // 5 * log2(e)
#define SROW2 40                 // chunk row: 32 data + 8 pad shorts
#define BUFB  10240              // one chunk buffer: 128*40*2 bytes

// ---------------- device scratch ----------------
__device__ __align__(16) __nv_bfloat16 g_hi[(size_t)NN * DD];   // normalized bf16
__device__ __align__(16) __nv_bfloat16 g_sc[(size_t)NN * DD];   // normalized * 5*log2(e)
__device__ unsigned g_rm[NN];
__device__ int      g_hq[NN];
__device__ double   g_denom;
__device__ double   g_pos;
__device__ int      g_is64;

// bf16 tensor-core mma (sm_80+ baseline PTX)
__device__ __forceinline__ void mma16816(float* c, const uint32_t* a, const uint32_t* b) {
    asm volatile(
        "mma.sync.aligned.m16n8k16.row.col.f32.bf16.bf16.f32 "
        "{%0,%1,%2,%3}, {%4,%5,%6,%7}, {%8,%9}, {%0,%1,%2,%3};"
        : "+f"(c[0]), "+f"(c[1]), "+f"(c[2]), "+f"(c[3])
        : "r"(a[0]), "r"(a[1]), "r"(a[2]), "r"(a[3]), "r"(b[0]), "r"(b[1]));
}
__device__ __forceinline__ void ldsm4(uint32_t& r0, uint32_t& r1, uint32_t& r2, uint32_t& r3,
                                      uint32_t addr) {
    asm volatile("ldmatrix.sync.aligned.m8n8.x4.shared.b16 {%0,%1,%2,%3}, [%4];"
                 : "=r"(r0), "=r"(r1), "=r"(r2), "=r"(r3) : "r"(addr));
}
__device__ __forceinline__ uint32_t smem_u32(const void* p) {
    uint32_t a;
    asm("{ .reg .u64 t; cvta.to.shared.u64 t, %1; cvt.u32.u64 %0, t; }" : "=r"(a) : "l"(p));
    return a;
}
__device__ __forceinline__ void cpa16(uint32_t d, const void* s) {
    asm volatile("cp.async.cg.shared.global [%0], [%1], 16;" :: "r"(d), "l"(s) : "memory");
}
#define CPA_COMMIT() asm volatile("cp.async.commit_group;" ::: "memory")
#define CPA_WAIT(n)  asm volatile("cp.async.wait_group %0;" :: "n"(n) : "memory")
__device__ __forceinline__ float ex2f(float x) {
    float r;
    asm("ex2.approx.f32 %0, %1;" : "=f"(r) : "f"(x));
    return r;
}

// ---------------- init: zero accumulators + detect int32 vs int64 --------
__global__ void k_init(const int* __restrict__ nq32) {
    int found = 0;
    for (int w = 2 * threadIdx.x + 1; w < 4096; w += 512)
        found |= (nq32[w] != 0);
    int any = __syncthreads_or(found);
    if (threadIdx.x == 0) {
        g_is64  = !any;
        g_denom = 0.0;
        g_pos   = 0.0;
    }
}

// ---------------- normalize + bf16 round (+ scaled copy) + pos dot --------
__global__ void k_norm(const float* __restrict__ x, const float* __restrict__ xa) {
    int r = blockIdx.x;
    int t = threadIdx.x;                         // 0..127
    float xv = x[(size_t)r * DD + t];
    float av = xa[(size_t)r * DD + t];
    float sx = xv * xv, sa = av * av, sd = xv * av;
    #pragma unroll
    for (int o = 16; o; o >>= 1) {
        sx += __shfl_xor_sync(0xFFFFFFFFu, sx, o);
        sa += __shfl_xor_sync(0xFFFFFFFFu, sa, o);
        sd += __shfl_xor_sync(0xFFFFFFFFu, sd, o);
    }
    __shared__ float wsx[4], wsa[4], wsd[4];
    int w = t >> 5, l = t & 31;
    if (l == 0) { wsx[w] = sx; wsa[w] = sa; wsd[w] = sd; }
    __syncthreads();
    sx = wsx[0] + wsx[1] + wsx[2] + wsx[3];
    sa = wsa[0] + wsa[1] + wsa[2] + wsa[3];
    sd = wsd[0] + wsd[1] + wsd[2] + wsd[3];
    float inx = rsqrtf(sx), ina = rsqrtf(sa);

    float v1 = xv * inx, v2 = av * ina;
    g_hi[(size_t)r * DD + t]        = __float2bfloat16(v1);
    g_hi[(size_t)(BB + r) * DD + t] = __float2bfloat16(v2);
    g_sc[(size_t)r * DD + t]        = __float2bfloat16(v1 * L2E5);
    g_sc[(size_t)(BB + r) * DD + t] = __float2bfloat16(v2 * L2E5);
    if (t == 0) atomicAdd(&g_pos, (double)(sd * inx * ina));
}

// ---------------- cluster masks -------------------------------------------
__global__ void k_mask(const void* __restrict__ hq, const void* __restrict__ nq, int K) {
    int n = blockIdx.x * blockDim.x + threadIdx.x;
    if (n >= NN) return;
    int is64 = g_is64;
    int hv = is64 ? (int)((const long long*)hq)[n] : ((const int*)hq)[n];
    unsigned m = 0;
    for (int k = 0; k < K; k++) {
        int v = is64 ? (int)((const long long*)nq)[(size_t)n * K + k]
                     : ((const int*)nq)[(size_t)n * K + k];
        m |= (1u << (v & 31));
    }
    g_hq[n] = hv & 31;
    g_rm[n] = m;
}

// ---------------- fused GEMM(HMMA) + exp + masked sum (upper triangle) ----
// Block 128x128, 128 thr = 4 warps (2m x 2n), warp tile 64x64.
// A = g_sc (pre-scaled by 5*log2 e), B = g_hi -> acc is the ex2 argument.
// K as 4 chunks of 32, cp.async double-buffered. Predicated-add epilogue.
__global__ void __launch_bounds__(128) k_main() {
    int bi = blockIdx.y, bj = blockIdx.x;
    if (bj < bi) return;                       // symmetric: only bj >= bi

    __shared__ __align__(16) unsigned short As2[2][128][SROW2];
    __shared__ __align__(16) unsigned short Bs2[2][128][SROW2];
    __shared__ unsigned rmI[128], rmJ[128];
    __shared__ unsigned char hqI[128], hqJ[128];
    __shared__ float    red[4];

    int tid  = threadIdx.x;
    int wid  = tid >> 5, lane = tid & 31;
    int wm   = wid & 1,  wn   = wid >> 1;      // 2 x 2 warps
    int g    = lane >> 2, t4  = lane & 3;

    rmI[tid] = g_rm[bi * 128 + tid];
    rmJ[tid] = g_rm[bj * 128 + tid];
    hqI[tid] = (unsigned char)g_hq[bi * 128 + tid];
    hqJ[tid] = (unsigned char)g_hq[bj * 128 + tid];

    float acc[4][8][4];                        // [mb][nb][reg]
    #pragma unroll
    for (int mb = 0; mb < 4; mb++)
        #pragma unroll
        for (int nb = 0; nb < 8; nb++)
            #pragma unroll
            for (int r = 0; r < 4; r++) acc[mb][nb][r] = 0.f;

    const uint4* Agl = (const uint4*)(g_sc + (size_t)bi * 128 * DD);
    const uint4* Bgl = (const uint4*)(g_hi + (size_t)bj * 128 * DD);
    uint32_t smA = smem_u32(&As2[0][0][0]);
    uint32_t smB = smem_u32(&Bs2[0][0][0]);

    int m0 = wm * 64, n0 = wn * 64;
    uint32_t arow = smA + (uint32_t)((m0 + (lane & 15)) * (SROW2 * 2))
                  + (uint32_t)((lane >> 4) << 4);
    uint32_t brow = smB + (uint32_t)((n0 + ((lane >> 4) << 3) + (lane & 7)) * (SROW2 * 2))
                  + (uint32_t)(((lane >> 3) & 1) << 4);

    #define LOAD_CHUNK(c, f)                                              \
        do {                                                              \
            _Pragma("unroll")                                             \
            for (int it = 0; it < 4; it++) {                              \
                int idx = tid + it * 128;                                 \
                int rr2 = idx >> 2, qq = idx & 3;                         \
                uint32_t off = (uint32_t)(f) * BUFB                       \
                             + (uint32_t)(rr2 * (SROW2 * 2) + qq * 16);   \
                cpa16(smA + off, Agl + rr2 * 16 + (c) * 4 + qq);          \
                cpa16(smB + off, Bgl + rr2 * 16 + (c) * 4 + qq);          \
            }                                                             \
            CPA_COMMIT();                                                 \
        } while (0)

    LOAD_CHUNK(0, 0);

    #pragma unroll
    for (int c = 0; c < 4; c++) {
        if (c < 3) {
            LOAD_CHUNK(c + 1, (c + 1) & 1);
            CPA_WAIT(1);
        } else {
            CPA_WAIT(0);
        }
        __syncthreads();
        uint32_t boff = (uint32_t)(c & 1) * BUFB;
        #pragma unroll
        for (int ks = 0; ks < 2; ks++) {
            uint32_t koff = boff + (uint32_t)(ks * 32);
            uint32_t b[8][2];
            #pragma unroll
            for (int nbp = 0; nbp < 4; nbp++)
                ldsm4(b[2 * nbp][0], b[2 * nbp][1], b[2 * nbp + 1][0], b[2 * nbp + 1][1],
                      brow + (uint32_t)(nbp * 16 * (SROW2 * 2)) + koff);
            uint32_t a[4][4];
            #pragma unroll
            for (int mb = 0; mb < 4; mb++)
                ldsm4(a[mb][0], a[mb][1], a[mb][2], a[mb][3],
                      arow + (uint32_t)(mb * 16 * (SROW2 * 2)) + koff);
            #pragma unroll
            for (int mb = 0; mb < 4; mb++)
                #pragma unroll
                for (int nb = 0; nb < 8; nb++)
                    mma16816(acc[mb][nb], a[mb], b[nb]);
        }
        __syncthreads();
    }
    #undef LOAD_CHUNK

    // ---- epilogue: predicated adds; per-row masks in registers ----
    unsigned rmi8[8], mr8[8];
    int      row8[8];
    float    t8[8];
    #pragma unroll
    for (int mb = 0; mb < 4; mb++)
        #pragma unroll
        for (int rr = 0; rr < 2; rr++) {
            int k = mb * 2 + rr;
            row8[k] = m0 + mb * 16 + g + rr * 8;
            rmi8[k] = rmI[row8[k]];
            mr8[k]  = 1u << hqI[row8[k]];
            t8[k]   = 0.f;
        }

    if (bi != bj) {
        #pragma unroll
        for (int nb = 0; nb < 8; nb++)
            #pragma unroll
            for (int rc = 0; rc < 2; rc++) {
                int col = n0 + nb * 8 + 2 * t4 + rc;
                unsigned rmj = rmJ[col];
                unsigned mc  = 1u << hqJ[col];
                #pragma unroll
                for (int k = 0; k < 8; k++) {
                    float e = ex2f(acc[k >> 1][nb][(k & 1) * 2 + rc]);
                    if (rmi8[k] & mc)  t8[k] += e;
                    if (rmj & mr8[k])  t8[k] += e;
                }
            }
    } else {
        #pragma unroll
        for (int nb = 0; nb < 8; nb++)
            #pragma unroll
            for (int rc = 0; rc < 2; rc++) {
                int col = n0 + nb * 8 + 2 * t4 + rc;
                unsigned rmj = rmJ[col];
                unsigned mc  = 1u << hqJ[col];
                #pragma unroll
                for (int k = 0; k < 8; k++) {
                    if (row8[k] < col) {
                        float e = ex2f(acc[k >> 1][nb][(k & 1) * 2 + rc]);
                        if (rmi8[k] & mc)  t8[k] += e;
                        if (rmj & mr8[k])  t8[k] += e;
                    }
                }
            }
    }

    float tsum = ((t8[0] + t8[1]) + (t8[2] + t8[3]))
               + ((t8[4] + t8[5]) + (t8[6] + t8[7]));
    #pragma unroll
    for (int o = 16; o; o >>= 1) tsum += __shfl_xor_sync(0xFFFFFFFFu, tsum, o);
    if (lane == 0) red[wid] = tsum;
    __syncthreads();
    if (tid == 0)
        atomicAdd(&g_denom, (double)(red[0] + red[1] + red[2] + red[3]));
}

// ---------------- finalize -------------------------------------------------
__global__ void k_fin(float* out) {
    if (threadIdx.x == 0)
        out[0] = (float)(log(g_denom) - g_pos / ((double)BB * 0.2));
}

// ---------------- launch ---------------------------------------------------
extern "C" void kernel_launch(void* const* d_in, const int* in_sizes, int n_in,
                              void* d_out, int out_size) {
    const float* x  = (const float*)d_in[0];
    const float* xa = (const float*)d_in[1];
    const void*  hq = d_in[2];
    const void*  nq = d_in[3];
    int K = in_sizes[3] / NN;                 // 10

    k_init<<<1, 256>>>((const int*)nq);
    k_norm<<<BB, 128>>>(x, xa);
    k_mask<<<(NN + 255) / 256, 256>>>(hq, nq, K);
    k_main<<<dim3(128, 128), 128>>>();
    k_fin<<<1, 32>>>((float*)d_out);
}